// round 11
// baseline (speedup 1.0000x reference)
#include <cuda_runtime.h>
#include <cuda_fp16.h>
#include <math.h>
#include <stdint.h>

// Problem constants
#define BATCH   4
#define SEQ     2048
#define DMODEL  1024
#define DINNER  2048
#define DSTATE  64
#define MROWS   (BATCH*SEQ)      // 8192
#define CHUNK   128
#define NCHUNK  (SEQ/CHUNK)      // 16
#define NPROJ   256              // padded 129 -> 256

// ---------------- scratch (device globals; no allocation allowed) ----------
__device__ float g_xi  [MROWS*DINNER];    // full-precision xi (scans)
__device__ float g_z   [MROWS*DINNER];
__device__ float g_a   [MROWS];
__device__ float g_P   [BATCH*NCHUNK];
__device__ float g_hfin [BATCH*NCHUNK*DINNER];
__device__ float g_carry[BATCH*NCHUNK*DINNER];
__device__ float g_proj[MROWS*NPROJ];
// fragment-major (perm) fp16 operands
__device__ __half g_xAP  [MROWS*DMODEL];    // x, A-perm, K=1024
__device__ __half g_xirP [MROWS*DINNER];    // xi rounded, A-perm, K=2048
__device__ __half g_BrawP[MROWS*DSTATE];    // A-perm, K=64
__device__ __half g_CrawP[MROWS*DSTATE];    // A-perm, K=64
__device__ __half g_yP   [MROWS*DINNER];    // y rounded, A-perm, K=2048
__device__ __half g_WinB [DMODEL*2*DINNER]; // B-perm [K=1024][N=4096]
__device__ __half g_WxpB [DINNER*NPROJ];    // B-perm [K=2048][N=256] (padded)
__device__ __half g_WBB  [DSTATE*DINNER];   // B-perm [K=64][N=2048]
__device__ __half g_WCB  [DSTATE*DINNER];   // B-perm [K=64][N=2048]
__device__ __half g_WoutB[DINNER*DMODEL];   // B-perm [K=2048][N=1024]

// ---------------- helpers ----------------------------------------------------
__device__ __forceinline__ void cp_async16(uint32_t saddr, const void* gptr) {
    asm volatile("cp.async.cg.shared.global [%0], [%1], 16;" :: "r"(saddr), "l"(gptr));
}
__device__ __forceinline__ void cp_commit() {
    asm volatile("cp.async.commit_group;");
}
template<int N>
__device__ __forceinline__ void cp_wait() {
    asm volatile("cp.async.wait_group %0;" :: "n"(N));
}
__device__ __forceinline__ void mma_f16(
    float& c0, float& c1, float& c2, float& c3,
    unsigned a0, unsigned a1, unsigned a2, unsigned a3,
    unsigned b0, unsigned b1)
{
    asm volatile(
        "mma.sync.aligned.m16n8k16.row.col.f32.f16.f16.f32 "
        "{%0,%1,%2,%3}, {%4,%5,%6,%7}, {%8,%9}, {%0,%1,%2,%3};"
        : "+f"(c0), "+f"(c1), "+f"(c2), "+f"(c3)
        : "r"(a0), "r"(a1), "r"(a2), "r"(a3), "r"(b0), "r"(b1));
}

// fragment-major (m16n8k16 fp16) index helpers -> index into half array.
__device__ __forceinline__ size_t permAh(int m, int k, int K16) {
    size_t block = (size_t)(m >> 4) * K16 + (k >> 4);
    int lane = (m & 7) * 4 + ((k >> 1) & 3);
    int slot = ((m >> 3) & 1) + 2 * ((k >> 3) & 1);
    return block * 256 + (lane * 4 + slot) * 2 + (k & 1);
}
__device__ __forceinline__ size_t permBh(int k, int n, int K16) {
    size_t block = (size_t)(n >> 3) * K16 + (k >> 4);
    int lane = (n & 7) * 4 + ((k >> 1) & 3);
    int slot = (k >> 3) & 1;
    return block * 128 + (lane * 2 + slot) * 2 + (k & 1);
}

// ---------------- operand prep kernels ---------------------------------------
__global__ void permA_h_kernel(__half* __restrict__ dst,
                               const float* __restrict__ src, int K)
{
    int idx = blockIdx.x * 256 + threadIdx.x;
    int m = idx / K, k = idx % K;
    dst[permAh(m, k, K >> 4)] = __float2half_rn(src[idx]);
}

__global__ void permB_h_kernel(__half* __restrict__ dst,
                               const float* __restrict__ src,
                               int K, int N, int ldsrc, int ncols)
{
    int idx = blockIdx.x * 256 + threadIdx.x;   // K*N total
    int k = idx / N, n = idx % N;
    float v = (n < ncols) ? src[(size_t)k * ldsrc + n] : 0.f;
    dst[permBh(k, n, K >> 4)] = __float2half_rn(v);
}

// ---------------- fp16 mma.sync GEMM, frag-major smem, 3-stage cp.async ------
// C[M,N] = A@B fp16 in / fp32 accum+out. CTA 128x128, BK=16, 8 warps (2m x 4n).
// MODE 1 (GEMM1): col<DINNER -> xi(C0)+xirP(P0, perm K16=128); else z(C1).
#define STG_BYTES 8192           // per stage: A 4KB + B 4KB

template<int MODE>
__global__ void __launch_bounds__(256) h16gemm(
    const __half* __restrict__ Ap, const __half* __restrict__ Bp,
    float* __restrict__ C0, float* __restrict__ C1,
    __half* __restrict__ P0, int ldc, int K)
{
    __shared__ __align__(16) char smbuf[3 * STG_BYTES];   // 24KB

    const int tid  = threadIdx.x;
    const int warp = tid >> 5;
    const int lane = tid & 31;
    const int lq   = lane & 3;
    const int lr   = lane >> 2;
    const int m0   = blockIdx.y * 128;
    const int n0   = blockIdx.x * 128;
    const int K16  = K >> 4;
    const int wmg  = (warp >> 2) * 4;   // warp m16-block base
    const int wng  = (warp & 3) * 4;    // warp n8-block base

    const uint32_t sbase = (uint32_t)__cvta_generic_to_shared(smbuf);

    float acc[4][4][4];
#pragma unroll
    for (int i = 0; i < 4; i++)
#pragma unroll
        for (int j = 0; j < 4; j++)
#pragma unroll
            for (int c = 0; c < 4; c++) acc[i][j][c] = 0.f;

    auto stage = [&](int i, int s) {
        cp_async16(sbase + s * STG_BYTES + tid * 16,
            Ap + ((size_t)((m0 >> 4) + (tid >> 5)) * K16 + i) * 256 + (tid & 31) * 8);
        cp_async16(sbase + s * STG_BYTES + 4096 + tid * 16,
            Bp + ((size_t)((n0 >> 3) + (tid >> 4)) * K16 + i) * 128 + (tid & 15) * 8);
    };

    stage(0, 0); cp_commit();
    stage(1, 1); cp_commit();

    for (int i = 0; i < K16; i++) {
        if (i == K16 - 1) cp_wait<0>(); else cp_wait<1>();
        __syncthreads();
        if (i + 2 < K16) { stage(i + 2, (i + 2) % 3); cp_commit(); }

        const __half* sa = (const __half*)(smbuf + (i % 3) * STG_BYTES);
        const __half* sb = sa + 2048;

        uint4 af[4];
        uint2 bf[4];
#pragma unroll
        for (int mt = 0; mt < 4; mt++)
            af[mt] = *(const uint4*)(sa + (wmg + mt) * 256 + lane * 8);
#pragma unroll
        for (int nt = 0; nt < 4; nt++)
            bf[nt] = *(const uint2*)(sb + (wng + nt) * 128 + lane * 4);
#pragma unroll
        for (int mt = 0; mt < 4; mt++)
#pragma unroll
            for (int nt = 0; nt < 4; nt++)
                mma_f16(acc[mt][nt][0], acc[mt][nt][1], acc[mt][nt][2], acc[mt][nt][3],
                        af[mt].x, af[mt].y, af[mt].z, af[mt].w,
                        bf[nt].x, bf[nt].y);
    }

#pragma unroll
    for (int mt = 0; mt < 4; mt++) {
#pragma unroll
        for (int nt = 0; nt < 4; nt++) {
            int row = m0 + (warp >> 2) * 64 + mt * 16 + lr;
            int col = n0 + (warp & 3) * 32 + nt * 8 + lq * 2;
            float2 v0 = make_float2(acc[mt][nt][0], acc[mt][nt][1]);
            float2 v1 = make_float2(acc[mt][nt][2], acc[mt][nt][3]);
            if (MODE == 1) {
                if (col < DINNER) {
                    *(float2*)(C0 + (size_t)row * DINNER + col)       = v0;
                    *(float2*)(C0 + (size_t)(row + 8) * DINNER + col) = v1;
                    *(__half2*)(P0 + permAh(row,     col, 128)) = __floats2half2_rn(v0.x, v0.y);
                    *(__half2*)(P0 + permAh(row + 8, col, 128)) = __floats2half2_rn(v1.x, v1.y);
                } else {
                    *(float2*)(C1 + (size_t)row * DINNER + col - DINNER)       = v0;
                    *(float2*)(C1 + (size_t)(row + 8) * DINNER + col - DINNER) = v1;
                }
            } else {
                *(float2*)(C0 + (size_t)row * ldc + col)       = v0;
                *(float2*)(C0 + (size_t)(row + 8) * ldc + col) = v1;
            }
        }
    }
}

// ---------------- shared building blocks for fused GEMM3+scan kernels --------
// Stage a full K=64 operand pair: A-perm tile (8 m-blocks x 4 k-blocks, 16KB)
// and B-perm tile (16 n-blocks x 4 k-blocks, 16KB).
__device__ __forceinline__ void stage_ops64(uint32_t sA, const __half* Abase,
                                            uint32_t sB, const __half* Bbase,
                                            int tid)
{
#pragma unroll
    for (int r = 0; r < 4; r++) {
        int c = tid + r * 256;
        cp_async16(sA + c * 16, Abase + (size_t)(c >> 5) * 256 + (c & 31) * 8);
    }
#pragma unroll
    for (int r = 0; r < 4; r++) {
        int c = tid + r * 256;
        cp_async16(sB + c * 16, Bbase + (size_t)(c >> 4) * 128 + (c & 15) * 8);
    }
}

// 128x128x64 MMA from staged frag tiles -> fp32 tile[128][132] in smem.
#define TSTR 132
__device__ __forceinline__ void mma_tile64(const __half* smA, const __half* smB,
                                           float* tile, int warp, int lane)
{
    const int wmg = (warp >> 2) * 4, wng = (warp & 3) * 4;
    const int lq = lane & 3, lr = lane >> 2;
    float acc[4][4][4];
#pragma unroll
    for (int i = 0; i < 4; i++)
#pragma unroll
        for (int j = 0; j < 4; j++)
#pragma unroll
            for (int c = 0; c < 4; c++) acc[i][j][c] = 0.f;
#pragma unroll
    for (int kb = 0; kb < 4; kb++) {
        uint4 af[4];
        uint2 bf[4];
#pragma unroll
        for (int mt = 0; mt < 4; mt++)
            af[mt] = *(const uint4*)(smA + ((wmg + mt) * 4 + kb) * 256 + lane * 8);
#pragma unroll
        for (int nt = 0; nt < 4; nt++)
            bf[nt] = *(const uint2*)(smB + ((wng + nt) * 4 + kb) * 128 + lane * 4);
#pragma unroll
        for (int mt = 0; mt < 4; mt++)
#pragma unroll
            for (int nt = 0; nt < 4; nt++)
                mma_f16(acc[mt][nt][0], acc[mt][nt][1], acc[mt][nt][2], acc[mt][nt][3],
                        af[mt].x, af[mt].y, af[mt].z, af[mt].w,
                        bf[nt].x, bf[nt].y);
    }
#pragma unroll
    for (int mt = 0; mt < 4; mt++) {
#pragma unroll
        for (int nt = 0; nt < 4; nt++) {
            int row = (warp >> 2) * 64 + mt * 16 + lr;
            int col = (warp & 3) * 32 + nt * 8 + lq * 2;
            tile[row * TSTR + col]           = acc[mt][nt][0];
            tile[row * TSTR + col + 1]       = acc[mt][nt][1];
            tile[(row + 8) * TSTR + col]     = acc[mt][nt][2];
            tile[(row + 8) * TSTR + col + 1] = acc[mt][nt][3];
        }
    }
}

// ---------------- F1: fused (Bm tile = Braw@W_B) + local chunk scan ----------
// grid (DINNER/128, NCHUNK, BATCH), 256 threads.
#define F1_A   0
#define F1_B   16384
#define F1_T   32768
#define F1_AS  100352
#define F1_S0  100864
#define F1_TOTAL 101376

__global__ void __launch_bounds__(256) fused_scan1_kernel()
{
    extern __shared__ __align__(16) char sm[];
    const uint32_t sbase = (uint32_t)__cvta_generic_to_shared(sm);
    __half* smA = (__half*)(sm + F1_A);
    __half* smB = (__half*)(sm + F1_B);
    float*  tile = (float*)(sm + F1_T);
    float*  a_sm = (float*)(sm + F1_AS);
    float*  s0_sm = (float*)(sm + F1_S0);

    const int tid = threadIdx.x;
    const int warp = tid >> 5, lane = tid & 31;
    const int d0 = blockIdx.x * 128;
    const int c = blockIdx.y, b = blockIdx.z;
    const int mbase = b * SEQ + c * CHUNK;

    stage_ops64(sbase + F1_A, g_BrawP + (size_t)(mbase >> 4) * 4 * 256,
                sbase + F1_B, g_WBB + (size_t)(d0 >> 3) * 4 * 128, tid);
    cp_commit();
    if (tid < 128) a_sm[tid] = g_a[mbase + tid];
    cp_wait<0>();
    __syncthreads();

    mma_tile64(smA, smB, tile, warp, lane);
    __syncthreads();

    // segmented scan: half 0 -> t [0,64), half 1 -> t [64,128)
    const int col = tid & 127, half = tid >> 7;
    const float* xip = g_xi + (size_t)(mbase + half * 64) * DINNER + d0 + col;
    const float* tp  = tile + (half * 64) * TSTR + col;
    const float* ap  = a_sm + half * 64;
    float h = 0.f, p = 1.f;
#pragma unroll 4
    for (int t = 0; t < 64; t++) {
        float av = ap[t];
        h = fmaf(av, h, tp[t * TSTR] * xip[(size_t)t * DINNER]);
        p *= av;
    }
    if (half == 0) s0_sm[col] = h;
    __syncthreads();
    if (half == 1)
        g_hfin[(size_t)(b * NCHUNK + c) * DINNER + d0 + col] = fmaf(p, s0_sm[col], h);
}

// ---------------- F3: fused (Bm,Cm tiles) + full scan + y epilogue -----------
#define F3_AB  0
#define F3_AC  16384
#define F3_BB  32768
#define F3_BC  49152
#define F3_TB  65536
#define F3_TC  133120
#define F3_AS  200704
#define F3_S0  201216
#define F3_P0  201728
#define F3_TOTAL 202240

__global__ void __launch_bounds__(256) fused_scan3_kernel(const float* __restrict__ Dvec)
{
    extern __shared__ __align__(16) char sm[];
    const uint32_t sbase = (uint32_t)__cvta_generic_to_shared(sm);
    float* tileB = (float*)(sm + F3_TB);
    float* tileC = (float*)(sm + F3_TC);
    float* a_sm  = (float*)(sm + F3_AS);
    float* s0_sm = (float*)(sm + F3_S0);
    float* p0_sm = (float*)(sm + F3_P0);

    const int tid = threadIdx.x;
    const int warp = tid >> 5, lane = tid & 31;
    const int d0 = blockIdx.x * 128;
    const int c = blockIdx.y, b = blockIdx.z;
    const int mbase = b * SEQ + c * CHUNK;

    stage_ops64(sbase + F3_AB, g_BrawP + (size_t)(mbase >> 4) * 4 * 256,
                sbase + F3_BB, g_WBB + (size_t)(d0 >> 3) * 4 * 128, tid);
    stage_ops64(sbase + F3_AC, g_CrawP + (size_t)(mbase >> 4) * 4 * 256,
                sbase + F3_BC, g_WCB + (size_t)(d0 >> 3) * 4 * 128, tid);
    cp_commit();
    if (tid < 128) a_sm[tid] = g_a[mbase + tid];
    cp_wait<0>();
    __syncthreads();

    mma_tile64((__half*)(sm + F3_AB), (__half*)(sm + F3_BB), tileB, warp, lane);
    mma_tile64((__half*)(sm + F3_AC), (__half*)(sm + F3_BC), tileC, warp, lane);
    __syncthreads();

    const int col = tid & 127, half = tid >> 7;
    const float carry = g_carry[(size_t)(b * NCHUNK + c) * DINNER + d0 + col];

    // phase 1: half-0 threads compute first-segment (S0, P0) from zero init
    if (half == 0) {
        const float* xip = g_xi + (size_t)mbase * DINNER + d0 + col;
        float h = 0.f, p = 1.f;
#pragma unroll 4
        for (int t = 0; t < 64; t++) {
            float av = a_sm[t];
            h = fmaf(av, h, tileB[t * TSTR + col] * xip[(size_t)t * DINNER]);
            p *= av;
        }
        s0_sm[col] = h;
        p0_sm[col] = p;
    }
    __syncthreads();

    // phase 2: both halves run their 64 steps with correct carried state
    float h = (half == 0) ? carry : fmaf(p0_sm[col], carry, s0_sm[col]);
    const float Dd = Dvec[d0 + col];
    const int t0 = half * 64;
    const float* xip = g_xi + (size_t)(mbase + t0) * DINNER + d0 + col;
    const float* zp  = g_z  + (size_t)(mbase + t0) * DINNER + d0 + col;
#pragma unroll 2
    for (int t = 0; t < 64; t++) {
        float xiv = xip[(size_t)t * DINNER];
        h = fmaf(a_sm[t0 + t], h, tileB[(t0 + t) * TSTR + col] * xiv);
        float zv = zp[(size_t)t * DINNER];
        float sil = zv / (1.f + expf(-zv));
        g_yP[permAh(mbase + t0 + t, d0 + col, 128)] =
            __float2half_rn((tileC[(t0 + t) * TSTR + col] * h + Dd * xiv) * sil);
    }
}

// ---------------- proj epilogue: a / BrawP / CrawP from padded proj ----------
__global__ void __launch_bounds__(128) proj_epi_kernel(const float* __restrict__ A_log)
{
    int row = blockIdx.x;
    int tid = threadIdx.x;
    const float* pr = g_proj + (size_t)row * NPROJ;
    if (tid < 64)
        g_BrawP[permAh(row, tid, 4)] = __float2half_rn(pr[1 + tid]);
    else
        g_CrawP[permAh(row, tid - 64, 4)] = __float2half_rn(pr[65 + (tid - 64)]);
    if (tid == 0) {
        float x  = pr[0];
        float sp = fmaxf(x, 0.f) + log1pf(expf(-fabsf(x)));  // softplus
        g_a[row] = expf(-expf(A_log[0]) * sp);
    }
}

// ---------------- chunk products of a ---------------------------------------
__global__ void chunkprod_kernel()
{
    int i = blockIdx.x * blockDim.x + threadIdx.x;
    if (i < BATCH * NCHUNK) {
        float p = 1.f;
        int base = i * CHUNK;
        for (int t = 0; t < CHUNK; t++) p *= g_a[base + t];
        g_P[i] = p;
    }
}

// ---------------- pass 2: carry across chunks --------------------------------
__global__ void scan2_kernel()
{
    int gid = blockIdx.x * blockDim.x + threadIdx.x;
    int b = gid / DINNER, d = gid % DINNER;
    float carry = 0.f;
    for (int c = 0; c < NCHUNK; c++) {
        int i = b * NCHUNK + c;
        g_carry[(size_t)i * DINNER + d] = carry;
        carry = g_P[i] * carry + g_hfin[(size_t)i * DINNER + d];
    }
}

// ---------------- launch -----------------------------------------------------
extern "C" void kernel_launch(void* const* d_in, const int* in_sizes, int n_in,
                              void* d_out, int out_size)
{
    const float* x     = (const float*)d_in[0];
    const float* W_in  = (const float*)d_in[1];
    const float* W_xp  = (const float*)d_in[2];
    const float* W_B   = (const float*)d_in[3];
    const float* W_C   = (const float*)d_in[4];
    const float* W_out = (const float*)d_in[5];
    const float* Dv    = (const float*)d_in[6];
    const float* A_log = (const float*)d_in[7];
    float* out = (float*)d_out;

    float *p_xi, *p_z, *p_proj;
    __half *p_xAP, *p_xirP, *p_yP;
    __half *p_WinB, *p_WxpB, *p_WBB, *p_WCB, *p_WoutB;
    cudaGetSymbolAddress((void**)&p_xi,    g_xi);
    cudaGetSymbolAddress((void**)&p_z,     g_z);
    cudaGetSymbolAddress((void**)&p_proj,  g_proj);
    cudaGetSymbolAddress((void**)&p_xAP,   g_xAP);
    cudaGetSymbolAddress((void**)&p_xirP,  g_xirP);
    cudaGetSymbolAddress((void**)&p_yP,    g_yP);
    cudaGetSymbolAddress((void**)&p_WinB,  g_WinB);
    cudaGetSymbolAddress((void**)&p_WxpB,  g_WxpB);
    cudaGetSymbolAddress((void**)&p_WBB,   g_WBB);
    cudaGetSymbolAddress((void**)&p_WCB,   g_WCB);
    cudaGetSymbolAddress((void**)&p_WoutB, g_WoutB);

    cudaFuncSetAttribute(fused_scan1_kernel,
        cudaFuncAttributeMaxDynamicSharedMemorySize, F1_TOTAL);
    cudaFuncSetAttribute(fused_scan3_kernel,
        cudaFuncAttributeMaxDynamicSharedMemorySize, F3_TOTAL);

    // 0) operand prep (convert once to fp16 fragment-major layouts)
    permA_h_kernel<<<(MROWS * DMODEL) / 256, 256>>>(p_xAP, x, DMODEL);
    permB_h_kernel<<<(DMODEL * 2 * DINNER) / 256, 256>>>(
        p_WinB, W_in, DMODEL, 2 * DINNER, 2 * DINNER, 2 * DINNER);
    permB_h_kernel<<<(DINNER * NPROJ) / 256, 256>>>(
        p_WxpB, W_xp, DINNER, NPROJ, 129, 129);
    permB_h_kernel<<<(DSTATE * DINNER) / 256, 256>>>(
        p_WBB, W_B, DSTATE, DINNER, DINNER, DINNER);
    permB_h_kernel<<<(DSTATE * DINNER) / 256, 256>>>(
        p_WCB, W_C, DSTATE, DINNER, DINNER, DINNER);
    permB_h_kernel<<<(DINNER * DMODEL) / 256, 256>>>(
        p_WoutB, W_out, DINNER, DMODEL, DMODEL, DMODEL);

    // GEMM1: xz = x @ W_in -> xi | z (+ xir perm)   (8192 x 4096 x 1024)
    h16gemm<1><<<dim3((2 * DINNER) / 128, MROWS / 128), 256>>>(
        p_xAP, p_WinB, p_xi, p_z, p_xirP, DINNER, DMODEL);

    // GEMM2: proj = xi_r @ W_xp_pad   (8192 x 256 x 2048)
    h16gemm<0><<<dim3(NPROJ / 128, MROWS / 128), 256>>>(
        p_xirP, p_WxpB, p_proj, nullptr, nullptr, NPROJ, DINNER);
    proj_epi_kernel<<<MROWS, 128>>>(A_log);
    chunkprod_kernel<<<1, 64>>>();

    // F1: fused GEMM3-B + local chunk scan -> hfin
    fused_scan1_kernel<<<dim3(DINNER / 128, NCHUNK, BATCH), 256, F1_TOTAL>>>();

    // pass 2: inter-chunk carry
    scan2_kernel<<<32, 256>>>();

    // F3: fused GEMM3-B/C + full scan + y epilogue -> yP (fp16 perm)
    fused_scan3_kernel<<<dim3(DINNER / 128, NCHUNK, BATCH), 256, F3_TOTAL>>>(Dv);

    // GEMM4: out = y @ W_out   (8192 x 1024 x 2048)
    h16gemm<0><<<dim3(DMODEL / 128, MROWS / 128), 256>>>(
        p_yP, p_WoutB, out, nullptr, nullptr, DMODEL, DINNER);
}

// round 13
// speedup vs baseline: 1.1525x; 1.1525x over previous
#include <cuda_runtime.h>
#include <cuda_fp16.h>
#include <math.h>
#include <stdint.h>

// Problem constants
#define BATCH   4
#define SEQ     2048
#define DMODEL  1024
#define DINNER  2048
#define DSTATE  64
#define MROWS   (BATCH*SEQ)      // 8192
#define CHUNK   128
#define NCHUNK  (SEQ/CHUNK)      // 16
#define NPROJ   256              // padded 129 -> 256

// ---------------- scratch (device globals; no allocation allowed) ----------
__device__ float g_xi  [MROWS*DINNER];    // full-precision xi (scans)
__device__ float g_z   [MROWS*DINNER];
__device__ float g_a   [MROWS];
__device__ float g_P   [BATCH*NCHUNK];
__device__ float g_Bm  [MROWS*DINNER];
__device__ float g_Cm  [MROWS*DINNER];
__device__ float g_hfin [BATCH*NCHUNK*DINNER];
__device__ float g_carry[BATCH*NCHUNK*DINNER];
__device__ float g_proj[MROWS*NPROJ];
// fragment-major (perm) fp16 operands
__device__ __half g_xAP  [MROWS*DMODEL];    // x, A-perm, K=1024
__device__ __half g_xirP [MROWS*DINNER];    // xi rounded, A-perm, K=2048
__device__ __half g_BrawP[MROWS*DSTATE];    // A-perm, K=64
__device__ __half g_CrawP[MROWS*DSTATE];    // A-perm, K=64
__device__ __half g_yP   [MROWS*DINNER];    // y rounded, A-perm, K=2048
__device__ __half g_WinB [DMODEL*2*DINNER]; // B-perm [K=1024][N=4096]
__device__ __half g_WxpB [DINNER*NPROJ];    // B-perm [K=2048][N=256] (padded)
__device__ __half g_WBB  [DSTATE*DINNER];   // B-perm [K=64][N=2048]
__device__ __half g_WCB  [DSTATE*DINNER];   // B-perm [K=64][N=2048]
__device__ __half g_WoutB[DINNER*DMODEL];   // B-perm [K=2048][N=1024]

// ---------------- helpers ----------------------------------------------------
__device__ __forceinline__ void cp_async16(uint32_t saddr, const void* gptr) {
    asm volatile("cp.async.cg.shared.global [%0], [%1], 16;" :: "r"(saddr), "l"(gptr));
}
__device__ __forceinline__ void cp_commit() {
    asm volatile("cp.async.commit_group;");
}
template<int N>
__device__ __forceinline__ void cp_wait() {
    asm volatile("cp.async.wait_group %0;" :: "n"(N));
}
__device__ __forceinline__ void mma_f16(
    float& c0, float& c1, float& c2, float& c3,
    unsigned a0, unsigned a1, unsigned a2, unsigned a3,
    unsigned b0, unsigned b1)
{
    asm volatile(
        "mma.sync.aligned.m16n8k16.row.col.f32.f16.f16.f32 "
        "{%0,%1,%2,%3}, {%4,%5,%6,%7}, {%8,%9}, {%0,%1,%2,%3};"
        : "+f"(c0), "+f"(c1), "+f"(c2), "+f"(c3)
        : "r"(a0), "r"(a1), "r"(a2), "r"(a3), "r"(b0), "r"(b1));
}

// fragment-major (m16n8k16 fp16) index helpers -> index into half array.
__device__ __forceinline__ size_t permAh(int m, int k, int K16) {
    size_t block = (size_t)(m >> 4) * K16 + (k >> 4);
    int lane = (m & 7) * 4 + ((k >> 1) & 3);
    int slot = ((m >> 3) & 1) + 2 * ((k >> 3) & 1);
    return block * 256 + (lane * 4 + slot) * 2 + (k & 1);
}
__device__ __forceinline__ size_t permBh(int k, int n, int K16) {
    size_t block = (size_t)(n >> 3) * K16 + (k >> 4);
    int lane = (n & 7) * 4 + ((k >> 1) & 3);
    int slot = (k >> 3) & 1;
    return block * 128 + (lane * 2 + slot) * 2 + (k & 1);
}

// ---------------- operand prep kernels ---------------------------------------
__global__ void permA_h_kernel(__half* __restrict__ dst,
                               const float* __restrict__ src, int K)
{
    int idx = blockIdx.x * 256 + threadIdx.x;
    int m = idx / K, k = idx % K;
    dst[permAh(m, k, K >> 4)] = __float2half_rn(src[idx]);
}

__global__ void permB_h_kernel(__half* __restrict__ dst,
                               const float* __restrict__ src,
                               int K, int N, int ldsrc, int ncols)
{
    int idx = blockIdx.x * 256 + threadIdx.x;   // K*N total
    int k = idx / N, n = idx % N;
    float v = (n < ncols) ? src[(size_t)k * ldsrc + n] : 0.f;
    dst[permBh(k, n, K >> 4)] = __float2half_rn(v);
}

// ---------------- fp16 mma.sync GEMM, frag-major smem, 3-stage cp.async ------
// C[M,N] = A@B fp16 in / fp32 accum+out. CTA 128 x (NBLK*32), 8 warps
// (2m x 4n), warp tile 64 x (NBLK*8). NBLK=4 -> 128-wide CTA; NBLK=8 -> 256.
// MODE 0: generic; blockIdx.z selects (Ap,Bp,C0) vs (Ap2,Bp2,Cz).
// MODE 1 (GEMM1): col<DINNER -> xi(C0)+xirP(P0, perm K16=128); else z(C1).

template<int MODE, int NBLK>
__global__ void __launch_bounds__(256) h16gemm(
    const __half* __restrict__ Ap, const __half* __restrict__ Bp,
    const __half* __restrict__ Ap2, const __half* __restrict__ Bp2,
    float* __restrict__ C0, float* __restrict__ C1, float* __restrict__ Cz,
    __half* __restrict__ P0, int ldc, int K)
{
    constexpr int STG = 4096 + NBLK * 1024;        // A 4KB + B NBLK KB
    __shared__ __align__(16) char smbuf[3 * STG];

    const int tid  = threadIdx.x;
    const int warp = tid >> 5;
    const int lane = tid & 31;
    const int lq   = lane & 3;
    const int lr   = lane >> 2;
    const int m0   = blockIdx.y * 128;
    const int n0   = blockIdx.x * (NBLK * 32);
    const int K16  = K >> 4;
    const int wmg  = (warp >> 2) * 4;        // warp m16-block base
    const int wng  = (warp & 3) * NBLK;      // warp n8-block base

    const bool alt = (MODE == 0) && (blockIdx.z == 1);
    const __half* Asel = alt ? Ap2 : Ap;
    const __half* Bsel = alt ? Bp2 : Bp;
    float* Csel = alt ? Cz : C0;

    const uint32_t sbase = (uint32_t)__cvta_generic_to_shared(smbuf);

    float acc[4][NBLK][4];
#pragma unroll
    for (int i = 0; i < 4; i++)
#pragma unroll
        for (int j = 0; j < NBLK; j++)
#pragma unroll
            for (int c = 0; c < 4; c++) acc[i][j][c] = 0.f;

    // stage K16-chunk i into stage s. A: 8 m-blocks x 512B; B: NBLK*4 x 256B.
    auto stage = [&](int i, int s) {
        cp_async16(sbase + s * STG + tid * 16,
            Asel + ((size_t)((m0 >> 4) + (tid >> 5)) * K16 + i) * 256 + (tid & 31) * 8);
#pragma unroll
        for (int r = 0; r < NBLK / 4; r++) {
            int c = tid + r * 256;
            cp_async16(sbase + s * STG + 4096 + c * 16,
                Bsel + ((size_t)((n0 >> 3) + (c >> 4)) * K16 + i) * 128 + (c & 15) * 8);
        }
    };

    stage(0, 0); cp_commit();
    stage(1, 1); cp_commit();

    for (int i = 0; i < K16; i++) {
        if (i == K16 - 1) cp_wait<0>(); else cp_wait<1>();
        __syncthreads();
        if (i + 2 < K16) { stage(i + 2, (i + 2) % 3); cp_commit(); }

        const __half* sa = (const __half*)(smbuf + (i % 3) * STG);
        const __half* sb = sa + 2048;

        uint4 af[4];
        uint2 bf[NBLK];
#pragma unroll
        for (int mt = 0; mt < 4; mt++)
            af[mt] = *(const uint4*)(sa + (wmg + mt) * 256 + lane * 8);
#pragma unroll
        for (int nt = 0; nt < NBLK; nt++)
            bf[nt] = *(const uint2*)(sb + (wng + nt) * 128 + lane * 4);
#pragma unroll
        for (int mt = 0; mt < 4; mt++)
#pragma unroll
            for (int nt = 0; nt < NBLK; nt++)
                mma_f16(acc[mt][nt][0], acc[mt][nt][1], acc[mt][nt][2], acc[mt][nt][3],
                        af[mt].x, af[mt].y, af[mt].z, af[mt].w,
                        bf[nt].x, bf[nt].y);
    }

    // epilogue: c0=(row,col) c1=(row,col+1) c2/c3 at row+8
#pragma unroll
    for (int mt = 0; mt < 4; mt++) {
#pragma unroll
        for (int nt = 0; nt < NBLK; nt++) {
            int row = m0 + (warp >> 2) * 64 + mt * 16 + lr;
            int col = n0 + (warp & 3) * (NBLK * 8) + nt * 8 + lq * 2;
            float2 v0 = make_float2(acc[mt][nt][0], acc[mt][nt][1]);
            float2 v1 = make_float2(acc[mt][nt][2], acc[mt][nt][3]);
            if (MODE == 1) {
                if (col < DINNER) {
                    *(float2*)(C0 + (size_t)row * DINNER + col)       = v0;
                    *(float2*)(C0 + (size_t)(row + 8) * DINNER + col) = v1;
                    *(__half2*)(P0 + permAh(row,     col, 128)) = __floats2half2_rn(v0.x, v0.y);
                    *(__half2*)(P0 + permAh(row + 8, col, 128)) = __floats2half2_rn(v1.x, v1.y);
                } else {
                    *(float2*)(C1 + (size_t)row * DINNER + col - DINNER)       = v0;
                    *(float2*)(C1 + (size_t)(row + 8) * DINNER + col - DINNER) = v1;
                }
            } else {
                *(float2*)(Csel + (size_t)row * ldc + col)       = v0;
                *(float2*)(Csel + (size_t)(row + 8) * ldc + col) = v1;
            }
        }
    }
}

// ---------------- proj epilogue: a / BrawP / CrawP from padded proj ----------
__global__ void __launch_bounds__(128) proj_epi_kernel(const float* __restrict__ A_log)
{
    int row = blockIdx.x;
    int tid = threadIdx.x;
    const float* pr = g_proj + (size_t)row * NPROJ;
    if (tid < 64)
        g_BrawP[permAh(row, tid, 4)] = __float2half_rn(pr[1 + tid]);
    else
        g_CrawP[permAh(row, tid - 64, 4)] = __float2half_rn(pr[65 + (tid - 64)]);
    if (tid == 0) {
        float x  = pr[0];
        float sp = fmaxf(x, 0.f) + log1pf(expf(-fabsf(x)));  // softplus
        g_a[row] = expf(-expf(A_log[0]) * sp);
    }
}

// ---------------- chunk products of a ---------------------------------------
__global__ void chunkprod_kernel()
{
    int i = blockIdx.x * blockDim.x + threadIdx.x;
    if (i < BATCH * NCHUNK) {
        float p = 1.f;
        int base = i * CHUNK;
        for (int t = 0; t < CHUNK; t++) p *= g_a[base + t];
        g_P[i] = p;
    }
}

// ---------------- pass 1: local chunk scan -> chunk-final h -----------------
__global__ void __launch_bounds__(256) scan1_kernel()
{
    __shared__ float a_sm[CHUNK];
    int d = blockIdx.x * 256 + threadIdx.x;
    int c = blockIdx.y, b = blockIdx.z;
    int mbase = b * SEQ + c * CHUNK;
    if (threadIdx.x < CHUNK) a_sm[threadIdx.x] = g_a[mbase + threadIdx.x];
    __syncthreads();

    float h = 0.f;
    size_t off = (size_t)mbase * DINNER + d;
#pragma unroll 4
    for (int t = 0; t < CHUNK; t++) {
        size_t idx = off + (size_t)t * DINNER;
        h = fmaf(a_sm[t], h, g_Bm[idx] * g_xi[idx]);
    }
    g_hfin[(size_t)(b * NCHUNK + c) * DINNER + d] = h;
}

// ---------------- pass 2: carry across chunks --------------------------------
__global__ void scan2_kernel()
{
    int gid = blockIdx.x * blockDim.x + threadIdx.x;
    int b = gid / DINNER, d = gid % DINNER;
    float carry = 0.f;
    for (int c = 0; c < NCHUNK; c++) {
        int i = b * NCHUNK + c;
        g_carry[(size_t)i * DINNER + d] = carry;
        carry = g_P[i] * carry + g_hfin[(size_t)i * DINNER + d];
    }
}

// ---------------- pass 3: scan + fused y = (C*h + D*xi)*silu(z) --------------
// writes fp16 y directly in A-perm layout (GEMM4 operand, K16=128)
__global__ void __launch_bounds__(256) scan3_kernel(const float* __restrict__ Dvec)
{
    __shared__ float a_sm[CHUNK];
    int d = blockIdx.x * 256 + threadIdx.x;
    int c = blockIdx.y, b = blockIdx.z;
    int mbase = b * SEQ + c * CHUNK;
    if (threadIdx.x < CHUNK) a_sm[threadIdx.x] = g_a[mbase + threadIdx.x];
    __syncthreads();

    float h  = g_carry[(size_t)(b * NCHUNK + c) * DINNER + d];
    float Dd = Dvec[d];
    size_t off = (size_t)mbase * DINNER + d;
#pragma unroll 2
    for (int t = 0; t < CHUNK; t++) {
        size_t idx = off + (size_t)t * DINNER;
        float xiv = g_xi[idx];
        h = fmaf(a_sm[t], h, g_Bm[idx] * xiv);
        float zv  = g_z[idx];
        float sil = zv / (1.f + expf(-zv));
        g_yP[permAh(mbase + t, d, 128)] =
            __float2half_rn((g_Cm[idx] * h + Dd * xiv) * sil);
    }
}

// ---------------- launch -----------------------------------------------------
extern "C" void kernel_launch(void* const* d_in, const int* in_sizes, int n_in,
                              void* d_out, int out_size)
{
    const float* x     = (const float*)d_in[0];
    const float* W_in  = (const float*)d_in[1];
    const float* W_xp  = (const float*)d_in[2];
    const float* W_B   = (const float*)d_in[3];
    const float* W_C   = (const float*)d_in[4];
    const float* W_out = (const float*)d_in[5];
    const float* Dv    = (const float*)d_in[6];
    const float* A_log = (const float*)d_in[7];
    float* out = (float*)d_out;

    float *p_xi, *p_z, *p_Bm, *p_Cm, *p_proj;
    __half *p_xAP, *p_xirP, *p_BrawP, *p_CrawP, *p_yP;
    __half *p_WinB, *p_WxpB, *p_WBB, *p_WCB, *p_WoutB;
    cudaGetSymbolAddress((void**)&p_xi,    g_xi);
    cudaGetSymbolAddress((void**)&p_z,     g_z);
    cudaGetSymbolAddress((void**)&p_Bm,    g_Bm);
    cudaGetSymbolAddress((void**)&p_Cm,    g_Cm);
    cudaGetSymbolAddress((void**)&p_proj,  g_proj);
    cudaGetSymbolAddress((void**)&p_xAP,   g_xAP);
    cudaGetSymbolAddress((void**)&p_xirP,  g_xirP);
    cudaGetSymbolAddress((void**)&p_BrawP, g_BrawP);
    cudaGetSymbolAddress((void**)&p_CrawP, g_CrawP);
    cudaGetSymbolAddress((void**)&p_yP,    g_yP);
    cudaGetSymbolAddress((void**)&p_WinB,  g_WinB);
    cudaGetSymbolAddress((void**)&p_WxpB,  g_WxpB);
    cudaGetSymbolAddress((void**)&p_WBB,   g_WBB);
    cudaGetSymbolAddress((void**)&p_WCB,   g_WCB);
    cudaGetSymbolAddress((void**)&p_WoutB, g_WoutB);

    // 0) operand prep (convert once to fp16 fragment-major layouts)
    permA_h_kernel<<<(MROWS * DMODEL) / 256, 256>>>(p_xAP, x, DMODEL);
    permB_h_kernel<<<(DMODEL * 2 * DINNER) / 256, 256>>>(
        p_WinB, W_in, DMODEL, 2 * DINNER, 2 * DINNER, 2 * DINNER);
    permB_h_kernel<<<(DINNER * NPROJ) / 256, 256>>>(
        p_WxpB, W_xp, DINNER, NPROJ, 129, 129);
    permB_h_kernel<<<(DSTATE * DINNER) / 256, 256>>>(
        p_WBB, W_B, DSTATE, DINNER, DINNER, DINNER);
    permB_h_kernel<<<(DSTATE * DINNER) / 256, 256>>>(
        p_WCB, W_C, DSTATE, DINNER, DINNER, DINNER);
    permB_h_kernel<<<(DINNER * DMODEL) / 256, 256>>>(
        p_WoutB, W_out, DINNER, DMODEL, DMODEL, DMODEL);

    // GEMM1 (wide 128x256 tiles): xz = x @ W_in -> xi | z (+ xir perm)
    h16gemm<1, 8><<<dim3((2 * DINNER) / 256, MROWS / 128), 256>>>(
        p_xAP, p_WinB, nullptr, nullptr, p_xi, p_z, nullptr, p_xirP,
        DINNER, DMODEL);

    // GEMM2 (128x128): proj = xi_r @ W_xp_pad   (8192 x 256 x 2048)
    h16gemm<0, 4><<<dim3(NPROJ / 128, MROWS / 128), 256>>>(
        p_xirP, p_WxpB, nullptr, nullptr, p_proj, nullptr, nullptr, nullptr,
        NPROJ, DINNER);
    proj_epi_kernel<<<MROWS, 128>>>(A_log);
    chunkprod_kernel<<<1, 64>>>();

    // GEMM3 fused dual (blockIdx.z): z=0: Bm = Braw@W_B ; z=1: Cm = Craw@W_C
    h16gemm<0, 4><<<dim3(DINNER / 128, MROWS / 128, 2), 256>>>(
        p_BrawP, p_WBB, p_CrawP, p_WCB, p_Bm, nullptr, p_Cm, nullptr,
        DINNER, DSTATE);

    // chunked scan (high-occupancy, unfused)
    scan1_kernel<<<dim3(DINNER / 256, NCHUNK, BATCH), 256>>>();
    scan2_kernel<<<32, 256>>>();
    scan3_kernel<<<dim3(DINNER / 256, NCHUNK, BATCH), 256>>>(Dv);

    // GEMM4 (wide 128x256 tiles): out = y @ W_out   (8192 x 1024 x 2048)
    h16gemm<0, 8><<<dim3(DMODEL / 256, MROWS / 128), 256>>>(
        p_yP, p_WoutB, nullptr, nullptr, out, nullptr, nullptr, nullptr,
        DMODEL, DINNER);
}

// round 14
// speedup vs baseline: 1.2706x; 1.1025x over previous
#include <cuda_runtime.h>
#include <cuda_fp16.h>
#include <math.h>
#include <stdint.h>

// Problem constants
#define BATCH   4
#define SEQ     2048
#define DMODEL  1024
#define DINNER  2048
#define DSTATE  64
#define MROWS   (BATCH*SEQ)      // 8192
#define CHUNK   128
#define NCHUNK  (SEQ/CHUNK)      // 16
#define NPROJ   256              // padded 129 -> 256

// ---------------- scratch (device globals; no allocation allowed) ----------
__device__ float g_xi  [MROWS*DINNER];    // full-precision xi (scans)
__device__ float g_z   [MROWS*DINNER];
__device__ float g_a   [MROWS];
__device__ float g_P   [BATCH*NCHUNK];
__device__ float g_Bm  [MROWS*DINNER];
__device__ float g_Cm  [MROWS*DINNER];
__device__ float g_hfin [BATCH*NCHUNK*DINNER];
__device__ float g_carry[BATCH*NCHUNK*DINNER];
__device__ float g_proj[MROWS*NPROJ];
// fragment-major (perm) fp16 operands
__device__ __half g_xAP  [MROWS*DMODEL];    // x, A-perm, K=1024
__device__ __half g_xirP [MROWS*DINNER];    // xi rounded, A-perm, K=2048
__device__ __half g_BrawP[MROWS*DSTATE];    // A-perm, K=64
__device__ __half g_CrawP[MROWS*DSTATE];    // A-perm, K=64
__device__ __half g_yP   [MROWS*DINNER];    // y rounded, A-perm, K=2048
__device__ __half g_WinB [DMODEL*2*DINNER]; // B-perm [K=1024][N=4096]
__device__ __half g_WxpB [DINNER*NPROJ];    // B-perm [K=2048][N=256] (padded)
__device__ __half g_WBB  [DSTATE*DINNER];   // B-perm [K=64][N=2048]
__device__ __half g_WCB  [DSTATE*DINNER];   // B-perm [K=64][N=2048]
__device__ __half g_WoutB[DINNER*DMODEL];   // B-perm [K=2048][N=1024]

// ---------------- helpers ----------------------------------------------------
__device__ __forceinline__ void cp_async16(uint32_t saddr, const void* gptr) {
    asm volatile("cp.async.cg.shared.global [%0], [%1], 16;" :: "r"(saddr), "l"(gptr));
}
__device__ __forceinline__ void cp_commit() {
    asm volatile("cp.async.commit_group;");
}
template<int N>
__device__ __forceinline__ void cp_wait() {
    asm volatile("cp.async.wait_group %0;" :: "n"(N));
}
__device__ __forceinline__ void mma_f16(
    float& c0, float& c1, float& c2, float& c3,
    unsigned a0, unsigned a1, unsigned a2, unsigned a3,
    unsigned b0, unsigned b1)
{
    asm volatile(
        "mma.sync.aligned.m16n8k16.row.col.f32.f16.f16.f32 "
        "{%0,%1,%2,%3}, {%4,%5,%6,%7}, {%8,%9}, {%0,%1,%2,%3};"
        : "+f"(c0), "+f"(c1), "+f"(c2), "+f"(c3)
        : "r"(a0), "r"(a1), "r"(a2), "r"(a3), "r"(b0), "r"(b1));
}

// fragment-major (m16n8k16 fp16) index helpers -> index into half array.
__device__ __forceinline__ size_t permAh(int m, int k, int K16) {
    size_t block = (size_t)(m >> 4) * K16 + (k >> 4);
    int lane = (m & 7) * 4 + ((k >> 1) & 3);
    int slot = ((m >> 3) & 1) + 2 * ((k >> 3) & 1);
    return block * 256 + (lane * 4 + slot) * 2 + (k & 1);
}
__device__ __forceinline__ size_t permBh(int k, int n, int K16) {
    size_t block = (size_t)(n >> 3) * K16 + (k >> 4);
    int lane = (n & 7) * 4 + ((k >> 1) & 3);
    int slot = (k >> 3) & 1;
    return block * 128 + (lane * 2 + slot) * 2 + (k & 1);
}

// ---------------- operand prep kernels ---------------------------------------
__global__ void permA_h_kernel(__half* __restrict__ dst,
                               const float* __restrict__ src, int K)
{
    int idx = blockIdx.x * 256 + threadIdx.x;
    int m = idx / K, k = idx % K;
    dst[permAh(m, k, K >> 4)] = __float2half_rn(src[idx]);
}

__global__ void permB_h_kernel(__half* __restrict__ dst,
                               const float* __restrict__ src,
                               int K, int N, int ldsrc, int ncols)
{
    int idx = blockIdx.x * 256 + threadIdx.x;   // K*N total
    int k = idx / N, n = idx % N;
    float v = (n < ncols) ? src[(size_t)k * ldsrc + n] : 0.f;
    dst[permBh(k, n, K >> 4)] = __float2half_rn(v);
}

// dual variant: blockIdx.y selects (dst1,src1) vs (dst2,src2) — W_B / W_C
__global__ void permB_h_dual_kernel(__half* __restrict__ dst1,
                                    const float* __restrict__ src1,
                                    __half* __restrict__ dst2,
                                    const float* __restrict__ src2,
                                    int K, int N)
{
    __half* dst = blockIdx.y ? dst2 : dst1;
    const float* src = blockIdx.y ? src2 : src1;
    int idx = blockIdx.x * 256 + threadIdx.x;
    int k = idx / N, n = idx % N;
    dst[permBh(k, n, K >> 4)] = __float2half_rn(src[(size_t)k * N + n]);
}

// ---------------- fp16 mma.sync GEMM: BK=32 mainloop, 3-stage cp.async -------
// C[M,N] = A@B fp16 in / fp32 accum+out. CTA 128x128, 8 warps (2m x 4n),
// warp tile 64x32, two k16-chunks per stage (BK=32).
// MODE 0: generic; blockIdx.z selects (Ap,Bp,C0) vs (Ap2,Bp2,Cz).
// MODE 1 (GEMM1): col<DINNER -> xi(C0)+xirP(P0, perm K16=128); else z(C1).
#define STG_BYTES 16384          // per stage: A 8KB + B 8KB (2 k-chunks)

template<int MODE>
__global__ void __launch_bounds__(256) h16gemm(
    const __half* __restrict__ Ap, const __half* __restrict__ Bp,
    const __half* __restrict__ Ap2, const __half* __restrict__ Bp2,
    float* __restrict__ C0, float* __restrict__ C1, float* __restrict__ Cz,
    __half* __restrict__ P0, int ldc, int K)
{
    __shared__ __align__(16) char smbuf[3 * STG_BYTES];   // 48KB

    const int tid  = threadIdx.x;
    const int warp = tid >> 5;
    const int lane = tid & 31;
    const int lq   = lane & 3;
    const int lr   = lane >> 2;
    const int m0   = blockIdx.y * 128;
    const int n0   = blockIdx.x * 128;
    const int K16  = K >> 4;
    const int K32  = K >> 5;
    const int wmg  = (warp >> 2) * 4;   // warp m16-block base
    const int wng  = (warp & 3) * 4;    // warp n8-block base

    const bool alt = (MODE == 0) && (blockIdx.z == 1);
    const __half* Asel = alt ? Ap2 : Ap;
    const __half* Bsel = alt ? Bp2 : Bp;
    float* Csel = alt ? Cz : C0;

    const uint32_t sbase = (uint32_t)__cvta_generic_to_shared(smbuf);

    float acc[4][4][4];
#pragma unroll
    for (int i = 0; i < 4; i++)
#pragma unroll
        for (int j = 0; j < 4; j++)
#pragma unroll
            for (int c = 0; c < 4; c++) acc[i][j][c] = 0.f;

    // stage BK=32 chunk i (k16-chunks 2i, 2i+1) into stage s.
    // smem A: m-block mb at [mb*512 .. +512) halfs (chunk0 256, chunk1 256)
    // smem B: n-block nb at 8KB + [nb*256 .. +256) halfs
    auto stage = [&](int i, int s) {
#pragma unroll
        for (int r = 0; r < 2; r++) {
            int c = tid + r * 256;           // 512 A 16B-chunks
            cp_async16(sbase + s * STG_BYTES + c * 16,
                Asel + ((size_t)((m0 >> 4) + (c >> 6)) * K16 + 2 * i) * 256 + (c & 63) * 8);
        }
#pragma unroll
        for (int r = 0; r < 2; r++) {
            int c = tid + r * 256;           // 512 B 16B-chunks
            cp_async16(sbase + s * STG_BYTES + 8192 + c * 16,
                Bsel + ((size_t)((n0 >> 3) + (c >> 5)) * K16 + 2 * i) * 128 + (c & 31) * 8);
        }
    };

    stage(0, 0); cp_commit();
    if (K32 > 1) { stage(1, 1); cp_commit(); }

    for (int i = 0; i < K32; i++) {
        if (i >= K32 - 2) cp_wait<0>(); else cp_wait<1>();
        __syncthreads();
        if (i + 2 < K32) { stage(i + 2, (i + 2) % 3); cp_commit(); }

        const __half* sa = (const __half*)(smbuf + (i % 3) * STG_BYTES);
        const __half* sb = sa + 4096;

#pragma unroll
        for (int kc = 0; kc < 2; kc++) {
            uint4 af[4];
            uint2 bf[4];
#pragma unroll
            for (int mt = 0; mt < 4; mt++)
                af[mt] = *(const uint4*)(sa + (wmg + mt) * 512 + kc * 256 + lane * 8);
#pragma unroll
            for (int nt = 0; nt < 4; nt++)
                bf[nt] = *(const uint2*)(sb + (wng + nt) * 256 + kc * 128 + lane * 4);
#pragma unroll
            for (int mt = 0; mt < 4; mt++)
#pragma unroll
                for (int nt = 0; nt < 4; nt++)
                    mma_f16(acc[mt][nt][0], acc[mt][nt][1], acc[mt][nt][2], acc[mt][nt][3],
                            af[mt].x, af[mt].y, af[mt].z, af[mt].w,
                            bf[nt].x, bf[nt].y);
        }
        __syncthreads();
    }

    // epilogue: c0=(row,col) c1=(row,col+1) c2/c3 at row+8
#pragma unroll
    for (int mt = 0; mt < 4; mt++) {
#pragma unroll
        for (int nt = 0; nt < 4; nt++) {
            int row = m0 + (warp >> 2) * 64 + mt * 16 + lr;
            int col = n0 + (warp & 3) * 32 + nt * 8 + lq * 2;
            float2 v0 = make_float2(acc[mt][nt][0], acc[mt][nt][1]);
            float2 v1 = make_float2(acc[mt][nt][2], acc[mt][nt][3]);
            if (MODE == 1) {
                if (col < DINNER) {
                    *(float2*)(C0 + (size_t)row * DINNER + col)       = v0;
                    *(float2*)(C0 + (size_t)(row + 8) * DINNER + col) = v1;
                    *(__half2*)(P0 + permAh(row,     col, 128)) = __floats2half2_rn(v0.x, v0.y);
                    *(__half2*)(P0 + permAh(row + 8, col, 128)) = __floats2half2_rn(v1.x, v1.y);
                } else {
                    *(float2*)(C1 + (size_t)row * DINNER + col - DINNER)       = v0;
                    *(float2*)(C1 + (size_t)(row + 8) * DINNER + col - DINNER) = v1;
                }
            } else {
                *(float2*)(Csel + (size_t)row * ldc + col)       = v0;
                *(float2*)(Csel + (size_t)(row + 8) * ldc + col) = v1;
            }
        }
    }
}

// ---------------- proj epilogue: a / BrawP / CrawP from padded proj ----------
__global__ void __launch_bounds__(128) proj_epi_kernel(const float* __restrict__ A_log)
{
    int row = blockIdx.x;
    int tid = threadIdx.x;
    const float* pr = g_proj + (size_t)row * NPROJ;
    if (tid < 64)
        g_BrawP[permAh(row, tid, 4)] = __float2half_rn(pr[1 + tid]);
    else
        g_CrawP[permAh(row, tid - 64, 4)] = __float2half_rn(pr[65 + (tid - 64)]);
    if (tid == 0) {
        float x  = pr[0];
        float sp = fmaxf(x, 0.f) + log1pf(expf(-fabsf(x)));  // softplus
        g_a[row] = expf(-expf(A_log[0]) * sp);
    }
}

// ---------------- chunk products of a ---------------------------------------
__global__ void chunkprod_kernel()
{
    int i = blockIdx.x * blockDim.x + threadIdx.x;
    if (i < BATCH * NCHUNK) {
        float p = 1.f;
        int base = i * CHUNK;
        for (int t = 0; t < CHUNK; t++) p *= g_a[base + t];
        g_P[i] = p;
    }
}

// ---------------- pass 1: local chunk scan -> chunk-final h -----------------
__global__ void __launch_bounds__(256) scan1_kernel()
{
    __shared__ float a_sm[CHUNK];
    int d = blockIdx.x * 256 + threadIdx.x;
    int c = blockIdx.y, b = blockIdx.z;
    int mbase = b * SEQ + c * CHUNK;
    if (threadIdx.x < CHUNK) a_sm[threadIdx.x] = g_a[mbase + threadIdx.x];
    __syncthreads();

    float h = 0.f;
    size_t off = (size_t)mbase * DINNER + d;
#pragma unroll 4
    for (int t = 0; t < CHUNK; t++) {
        size_t idx = off + (size_t)t * DINNER;
        h = fmaf(a_sm[t], h, g_Bm[idx] * g_xi[idx]);
    }
    g_hfin[(size_t)(b * NCHUNK + c) * DINNER + d] = h;
}

// ---------------- pass 2: carry across chunks --------------------------------
__global__ void scan2_kernel()
{
    int gid = blockIdx.x * blockDim.x + threadIdx.x;
    int b = gid / DINNER, d = gid % DINNER;
    float carry = 0.f;
    for (int c = 0; c < NCHUNK; c++) {
        int i = b * NCHUNK + c;
        g_carry[(size_t)i * DINNER + d] = carry;
        carry = g_P[i] * carry + g_hfin[(size_t)i * DINNER + d];
    }
}

// ---------------- pass 3: scan + fused y = (C*h + D*xi)*silu(z) --------------
// writes fp16 y directly in A-perm layout (GEMM4 operand, K16=128)
__global__ void __launch_bounds__(256) scan3_kernel(const float* __restrict__ Dvec)
{
    __shared__ float a_sm[CHUNK];
    int d = blockIdx.x * 256 + threadIdx.x;
    int c = blockIdx.y, b = blockIdx.z;
    int mbase = b * SEQ + c * CHUNK;
    if (threadIdx.x < CHUNK) a_sm[threadIdx.x] = g_a[mbase + threadIdx.x];
    __syncthreads();

    float h  = g_carry[(size_t)(b * NCHUNK + c) * DINNER + d];
    float Dd = Dvec[d];
    size_t off = (size_t)mbase * DINNER + d;
#pragma unroll 2
    for (int t = 0; t < CHUNK; t++) {
        size_t idx = off + (size_t)t * DINNER;
        float xiv = g_xi[idx];
        h = fmaf(a_sm[t], h, g_Bm[idx] * xiv);
        float zv  = g_z[idx];
        float sil = zv / (1.f + expf(-zv));
        g_yP[permAh(mbase + t, d, 128)] =
            __float2half_rn((g_Cm[idx] * h + Dd * xiv) * sil);
    }
}

// ---------------- launch -----------------------------------------------------
extern "C" void kernel_launch(void* const* d_in, const int* in_sizes, int n_in,
                              void* d_out, int out_size)
{
    const float* x     = (const float*)d_in[0];
    const float* W_in  = (const float*)d_in[1];
    const float* W_xp  = (const float*)d_in[2];
    const float* W_B   = (const float*)d_in[3];
    const float* W_C   = (const float*)d_in[4];
    const float* W_out = (const float*)d_in[5];
    const float* Dv    = (const float*)d_in[6];
    const float* A_log = (const float*)d_in[7];
    float* out = (float*)d_out;

    float *p_xi, *p_z, *p_Bm, *p_Cm, *p_proj;
    __half *p_xAP, *p_xirP, *p_BrawP, *p_CrawP, *p_yP;
    __half *p_WinB, *p_WxpB, *p_WBB, *p_WCB, *p_WoutB;
    cudaGetSymbolAddress((void**)&p_xi,    g_xi);
    cudaGetSymbolAddress((void**)&p_z,     g_z);
    cudaGetSymbolAddress((void**)&p_Bm,    g_Bm);
    cudaGetSymbolAddress((void**)&p_Cm,    g_Cm);
    cudaGetSymbolAddress((void**)&p_proj,  g_proj);
    cudaGetSymbolAddress((void**)&p_xAP,   g_xAP);
    cudaGetSymbolAddress((void**)&p_xirP,  g_xirP);
    cudaGetSymbolAddress((void**)&p_BrawP, g_BrawP);
    cudaGetSymbolAddress((void**)&p_CrawP, g_CrawP);
    cudaGetSymbolAddress((void**)&p_yP,    g_yP);
    cudaGetSymbolAddress((void**)&p_WinB,  g_WinB);
    cudaGetSymbolAddress((void**)&p_WxpB,  g_WxpB);
    cudaGetSymbolAddress((void**)&p_WBB,   g_WBB);
    cudaGetSymbolAddress((void**)&p_WCB,   g_WCB);
    cudaGetSymbolAddress((void**)&p_WoutB, g_WoutB);

    // 0) operand prep (convert once to fp16 fragment-major layouts)
    permA_h_kernel<<<(MROWS * DMODEL) / 256, 256>>>(p_xAP, x, DMODEL);
    permB_h_kernel<<<(DMODEL * 2 * DINNER) / 256, 256>>>(
        p_WinB, W_in, DMODEL, 2 * DINNER, 2 * DINNER, 2 * DINNER);
    permB_h_kernel<<<(DINNER * NPROJ) / 256, 256>>>(
        p_WxpB, W_xp, DINNER, NPROJ, 129, 129);
    permB_h_dual_kernel<<<dim3((DSTATE * DINNER) / 256, 2), 256>>>(
        p_WBB, W_B, p_WCB, W_C, DSTATE, DINNER);
    permB_h_kernel<<<(DINNER * DMODEL) / 256, 256>>>(
        p_WoutB, W_out, DINNER, DMODEL, DMODEL, DMODEL);

    // GEMM1: xz = x @ W_in -> xi | z (+ xir perm)   (8192 x 4096 x 1024)
    h16gemm<1><<<dim3((2 * DINNER) / 128, MROWS / 128), 256>>>(
        p_xAP, p_WinB, nullptr, nullptr, p_xi, p_z, nullptr, p_xirP,
        DINNER, DMODEL);

    // GEMM2: proj = xi_r @ W_xp_pad   (8192 x 256 x 2048)
    h16gemm<0><<<dim3(NPROJ / 128, MROWS / 128), 256>>>(
        p_xirP, p_WxpB, nullptr, nullptr, p_proj, nullptr, nullptr, nullptr,
        NPROJ, DINNER);
    proj_epi_kernel<<<MROWS, 128>>>(A_log);
    chunkprod_kernel<<<1, 64>>>();

    // GEMM3 fused dual (blockIdx.z): z=0: Bm = Braw@W_B ; z=1: Cm = Craw@W_C
    h16gemm<0><<<dim3(DINNER / 128, MROWS / 128, 2), 256>>>(
        p_BrawP, p_WBB, p_CrawP, p_WCB, p_Bm, nullptr, p_Cm, nullptr,
        DINNER, DSTATE);

    // chunked scan (high-occupancy, unfused)
    scan1_kernel<<<dim3(DINNER / 256, NCHUNK, BATCH), 256>>>();
    scan2_kernel<<<32, 256>>>();
    scan3_kernel<<<dim3(DINNER / 256, NCHUNK, BATCH), 256>>>(Dv);

    // GEMM4: out = y @ W_out   (8192 x 1024 x 2048)
    h16gemm<0><<<dim3(DMODEL / 128, MROWS / 128), 256>>>(
        p_yP, p_WoutB, nullptr, nullptr, out, nullptr, nullptr, nullptr,
        DMODEL, DINNER);
}